// round 11
// baseline (speedup 1.0000x reference)
#include <cuda_runtime.h>
#include <math.h>

#define Bq 8
#define Tq 2048
#define Dq 128
#define Kq 32
#define Nq 32
#define HNq 16
#define Mq 128
#define Lq 32
#define Cq 64            // Tq / Lq
#define ROWS (Bq*Tq)     // 16384 GEMM rows
#define KD2 1024         // GEMM inner dim after conjugate folding (32k * 32)

// ---------------- device scratch (static; no allocation at launch) ----------
__device__ float  g_xp[Bq][Kq][Tq];          // projected input [b][k][t]
__device__ float2 g_lam[Kq][Nq];
__device__ float2 g_lamL[Kq][Nq];
__device__ float2 g_Bp[Kq][Nq];
__device__ float  g_C[KD2][Mq];              // row k*32+j (j<16): Cr_j+Cr_{j+16}; row k*32+16+j: Ci_{j+16}-Ci_j
__device__ float  g_A[(size_t)ROWS * KD2];   // folded state matrix (67 MB)

#define FMA2(d, a, b) asm("fma.rn.f32x2 %0, %1, %2, %0;" : "+l"(d) : "l"(a), "l"(b))

// ---------------- K0: lambda/lamL/Bp (blocks 0..31) + folded C (blocks 32..) -
__global__ void k_precp(const float* __restrict__ theta,
                        const float* __restrict__ lnr,
                        const float* __restrict__ lni) {
    const int bx = blockIdx.x;
    if (bx < Kq) {
        if (threadIdx.x >= Nq) return;
        const int k = bx;
        const int j = threadIdx.x;
        __shared__ float th[HNq];
        if (j < HNq) th[j] = theta[k * HNq + j];
        __syncwarp(0xFFFFFFFF);

        const float phj = (j < HNq) ? th[j] : -th[j - HNq];
        g_lam[k][j] = make_float2(cosf(phj), sinf(phj));

        double aL  = (double)phj * 32.0;
        double red = aL - rint(aL * (0.5 / M_PI)) * (2.0 * M_PI);
        float  rf  = (float)red;
        g_lamL[k][j] = make_float2(cosf(rf), sinf(rf));

        // lnBp = -sum_{i != j} log(1 - e^{i(th_i - th_j)});
        // 1 - e^{id} = 2 sin(d/2) e^{i(d/2 - sgn(d) pi/2)}   (fp32 trig only)
        float  lr  = 0.0f;
        double liD = 0.0;
        #pragma unroll
        for (int i = 0; i < Nq; i++) {
            if (i == j) continue;
            float phi = (i < HNq) ? th[i] : -th[i - HNq];
            float d   = phi - phj;
            float s   = sinf(0.5f * d);
            lr  += logf(2.0f * fabsf(s));
            liD += (double)(0.5f * d) - copysign(0.5 * M_PI, (double)d);
        }
        double phiB = -liD;
        phiB -= rint(phiB * (0.5 / M_PI)) * (2.0 * M_PI);
        float mag = expf(-lr);
        float pb  = (float)phiB;
        g_Bp[k][j] = make_float2(mag * cosf(pb), mag * sinf(pb));
    } else {
        // folded C: one thread per (k, j<16, m); reads n=j and n=j+16
        int idx = (bx - Kq) * 256 + threadIdx.x;   // 0 .. 65535
        if (idx < Kq * HNq * Mq) {
            int k = idx >> 11;          // /(16*128)
            int j = (idx >> 7) & 15;
            int m = idx & 127;
            int i1 = (k * Nq + j) * Mq + m;
            int i2 = (k * Nq + j + HNq) * Mq + m;
            float r1 = expf(lnr[i1]), a1 = lni[i1];
            float r2 = expf(lnr[i2]), a2 = lni[i2];
            g_C[k * 32 + j][m]      = fmaf(r1, cosf(a1), r2 * cosf(a2));   // Cr_j + Cr_{j+16}
            g_C[k * 32 + 16 + j][m] = fmaf(r2, sinf(a2), -r1 * sinf(a1));  // Ci_{j+16} - Ci_j
        }
    }
}

// ---------------- K1: xp = x @ R, transposed to [b][k][t] --------------------
__global__ void k_xp(const float* __restrict__ x, const float* __restrict__ R) {
    __shared__ float xs[32][129];
    __shared__ float Rs[Dq][Kq];
    const int b  = blockIdx.y;
    const int t0 = blockIdx.x * 32;
    const int tid = threadIdx.x;

    for (int i = tid; i < Dq * Kq; i += 256) ((float*)Rs)[i] = R[i];
    for (int i = tid; i < 32 * Dq; i += 256) {
        int tl = i >> 7, d = i & 127;
        xs[tl][d] = x[((size_t)b * Tq + t0 + tl) * Dq + d];
    }
    __syncthreads();

    const int tl = tid & 31;
    const int k0 = tid >> 5;
    float acc[4] = {0.f, 0.f, 0.f, 0.f};
    for (int d = 0; d < Dq; d++) {
        float xv = xs[tl][d];
        #pragma unroll
        for (int j = 0; j < 4; j++) acc[j] = fmaf(xv, Rs[d][k0 + 8 * j], acc[j]);
    }
    #pragma unroll
    for (int j = 0; j < 4; j++) g_xp[b][k0 + 8 * j][t0 + tl] = acc[j];
}

// ---------------- K2: partials + cross-chunk scan + replay -> folded A -------
// lanes 16..31 compute the conjugate branch; their s.y = -si of partner lane.
__global__ __launch_bounds__(256) void k_states() {
    __shared__ float2 sP[Cq][Nq];
    __shared__ float2 sS[Cq][Nq];
    const int b = blockIdx.x >> 5;
    const int k = blockIdx.x & 31;
    const int lane = threadIdx.x & 31;
    const int w = threadIdx.x >> 5;

    const float2 lam = g_lam[k][lane];
    const float2 bp  = g_Bp[k][lane];

    for (int q = 0; q < 8; q++) {
        int c = w * 8 + q;
        const float* xp = &g_xp[b][k][c * Lq];
        float pr = 0.f, pi = 0.f;
        #pragma unroll
        for (int j = 0; j < Lq; j++) {
            float xv = xp[j];
            float nr = fmaf(lam.x, pr, fmaf(-lam.y, pi, bp.x * xv));
            float ni = fmaf(lam.y, pr, fmaf(lam.x, pi, bp.y * xv));
            pr = nr; pi = ni;
        }
        sP[c][lane] = make_float2(pr, pi);
    }
    __syncthreads();

    if (w == 0) {
        float2 lL = g_lamL[k][lane];
        float sr = 0.f, si = 0.f;
        for (int c = 0; c < Cq; c++) {
            sS[c][lane] = make_float2(sr, si);
            float2 p = sP[c][lane];
            float nr = fmaf(lL.x, sr, fmaf(-lL.y, si, p.x));
            float ni = fmaf(lL.y, sr, fmaf(lL.x, si, p.y));
            sr = nr; si = ni;
        }
    }
    __syncthreads();

    for (int q = 0; q < 8; q++) {
        int c = w * 8 + q;
        const float* xp = &g_xp[b][k][c * Lq];
        float2 s = sS[c][lane];
        size_t rb = ((size_t)b * Tq + c * Lq) * KD2 + k * 32;
        #pragma unroll
        for (int i = 0; i < Lq; i++) {
            // lane<16: sr_lane ; lane>=16: -s.y = si of (lane-16). One coalesced float per lane.
            g_A[rb + (size_t)i * KD2 + lane] = (lane < HNq) ? s.x : -s.y;
            float xv = xp[i];
            float nr = fmaf(lam.x, s.x, fmaf(-lam.y, s.y, bp.x * xv));
            float ni = fmaf(lam.y, s.x, fmaf(lam.x, s.y, bp.y * xv));
            s.x = nr; s.y = ni;
        }
    }
}

// ---------------- K3: SGEMM out = A[16384x1024] * C[1024x128] / 32 -----------
// 128 threads, block tile 64t x 64m, per-thread 8t x 4m, 4 blocks/SM (16 warps).
// Grid (256, 2) = 512 blocks -> fits in ONE wave (148 SMs x 4).
#define MT 64
#define KT 16
#define NT2 (KD2 / KT)   // 64

__global__ __launch_bounds__(128, 4) void k_gemm(float* __restrict__ out) {
    __shared__ float2 As[2][KT][66];    // dup (a,a), indexed [kk][t]
    __shared__ float  Cs[2][KT][68];    // natural, indexed [kk][m] (64 + pad)
    const int tid = threadIdx.x;
    const int tg = tid >> 4;            // 0..7  -> t rows tg*8..+7
    const int mg = tid & 15;            // 0..15 -> m cols mg*4..+3
    const size_t row0 = (size_t)blockIdx.x * MT;
    const int    cm0  = blockIdx.y * 64;           // m-half of C/out
    const float* Ab = g_A + row0 * KD2;

    const int ar = tid >> 1;            // 0..63 : A row
    const int ac = (tid & 1) * 8;       // 0/8   : kk offset
    const int cr = tid >> 3;            // 0..15 : C row (kk)
    const int cc = (tid & 7) * 8;       // C m offset within 64

    float4 av0, av1, cv0, cv1;
    av0 = *(const float4*)(Ab + (size_t)ar * KD2 + ac);
    av1 = *(const float4*)(Ab + (size_t)ar * KD2 + ac + 4);
    cv0 = *(const float4*)(&g_C[cr][cm0 + cc]);
    cv1 = *(const float4*)(&g_C[cr][cm0 + cc + 4]);
    As[0][ac + 0][ar] = make_float2(av0.x, av0.x);
    As[0][ac + 1][ar] = make_float2(av0.y, av0.y);
    As[0][ac + 2][ar] = make_float2(av0.z, av0.z);
    As[0][ac + 3][ar] = make_float2(av0.w, av0.w);
    As[0][ac + 4][ar] = make_float2(av1.x, av1.x);
    As[0][ac + 5][ar] = make_float2(av1.y, av1.y);
    As[0][ac + 6][ar] = make_float2(av1.z, av1.z);
    As[0][ac + 7][ar] = make_float2(av1.w, av1.w);
    *(float4*)(&Cs[0][cr][cc])     = cv0;
    *(float4*)(&Cs[0][cr][cc + 4]) = cv1;
    __syncthreads();

    unsigned long long acc[8][2];
    #pragma unroll
    for (int i = 0; i < 8; i++) { acc[i][0] = 0ull; acc[i][1] = 0ull; }

    for (int kt = 0; kt < NT2; kt++) {
        const int buf = kt & 1;
        if (kt + 1 < NT2) {
            int k0 = (kt + 1) * KT;
            av0 = *(const float4*)(Ab + (size_t)ar * KD2 + k0 + ac);
            av1 = *(const float4*)(Ab + (size_t)ar * KD2 + k0 + ac + 4);
            cv0 = *(const float4*)(&g_C[k0 + cr][cm0 + cc]);
            cv1 = *(const float4*)(&g_C[k0 + cr][cm0 + cc + 4]);
        }
        #pragma unroll
        for (int kk = 0; kk < KT; kk++) {
            ulonglong2 a01 = *(const ulonglong2*)&As[buf][kk][tg * 8 + 0];
            ulonglong2 a23 = *(const ulonglong2*)&As[buf][kk][tg * 8 + 2];
            ulonglong2 a45 = *(const ulonglong2*)&As[buf][kk][tg * 8 + 4];
            ulonglong2 a67 = *(const ulonglong2*)&As[buf][kk][tg * 8 + 6];
            ulonglong2 c01 = *(const ulonglong2*)&Cs[buf][kk][mg * 4];
            FMA2(acc[0][0], a01.x, c01.x); FMA2(acc[0][1], a01.x, c01.y);
            FMA2(acc[1][0], a01.y, c01.x); FMA2(acc[1][1], a01.y, c01.y);
            FMA2(acc[2][0], a23.x, c01.x); FMA2(acc[2][1], a23.x, c01.y);
            FMA2(acc[3][0], a23.y, c01.x); FMA2(acc[3][1], a23.y, c01.y);
            FMA2(acc[4][0], a45.x, c01.x); FMA2(acc[4][1], a45.x, c01.y);
            FMA2(acc[5][0], a45.y, c01.x); FMA2(acc[5][1], a45.y, c01.y);
            FMA2(acc[6][0], a67.x, c01.x); FMA2(acc[6][1], a67.x, c01.y);
            FMA2(acc[7][0], a67.y, c01.x); FMA2(acc[7][1], a67.y, c01.y);
        }
        if (kt + 1 < NT2) {
            const int nb = buf ^ 1;
            As[nb][ac + 0][ar] = make_float2(av0.x, av0.x);
            As[nb][ac + 1][ar] = make_float2(av0.y, av0.y);
            As[nb][ac + 2][ar] = make_float2(av0.z, av0.z);
            As[nb][ac + 3][ar] = make_float2(av0.w, av0.w);
            As[nb][ac + 4][ar] = make_float2(av1.x, av1.x);
            As[nb][ac + 5][ar] = make_float2(av1.y, av1.y);
            As[nb][ac + 6][ar] = make_float2(av1.z, av1.z);
            As[nb][ac + 7][ar] = make_float2(av1.w, av1.w);
            *(float4*)(&Cs[nb][cr][cc])     = cv0;
            *(float4*)(&Cs[nb][cr][cc + 4]) = cv1;
            __syncthreads();
        }
    }

    const float inv = 1.0f / 32.0f;
    #pragma unroll
    for (int i = 0; i < 8; i++) {
        float2 p0 = *reinterpret_cast<float2*>(&acc[i][0]);
        float2 p1 = *reinterpret_cast<float2*>(&acc[i][1]);
        float* op = out + (row0 + tg * 8 + i) * Mq + cm0 + mg * 4;
        *(float4*)(op) = make_float4(p0.x * inv, p0.y * inv, p1.x * inv, p1.y * inv);
    }
}

// ---------------- K4: out += xp @ D / 32 + Do --------------------------------
__global__ void k_dterm(const float* __restrict__ Dmat, const float* __restrict__ Dov,
                        float* __restrict__ out) {
    __shared__ float sxp[8][33];
    const int m   = threadIdx.x;
    const int bt0 = blockIdx.x * 8;
    for (int i = threadIdx.x; i < 8 * Kq; i += 128) {
        int r = i >> 5, k = i & 31;
        int bt = bt0 + r;
        sxp[r][k] = g_xp[bt >> 11][k][bt & 2047];
    }
    __syncthreads();
    float dov = Dov[m];
    for (int r = 0; r < 8; r++) {
        float acc = 0.f;
        #pragma unroll 8
        for (int k = 0; k < Kq; k++) acc = fmaf(sxp[r][k], Dmat[k * Mq + m], acc);
        size_t idx = (size_t)(bt0 + r) * Mq + m;
        out[idx] = out[idx] + fmaf(acc, 1.0f / 32.0f, dov);
    }
}

// ---------------- launch ------------------------------------------------------
extern "C" void kernel_launch(void* const* d_in, const int* in_sizes, int n_in,
                              void* d_out, int out_size) {
    const float* x     = (const float*)d_in[0];
    const float* R     = (const float*)d_in[1];
    const float* theta = (const float*)d_in[2];
    const float* lnC_r = (const float*)d_in[3];
    const float* lnC_i = (const float*)d_in[4];
    const float* Dmat  = (const float*)d_in[5];
    const float* Dov   = (const float*)d_in[6];
    float* out = (float*)d_out;

    k_precp<<<Kq + (Kq * HNq * Mq + 255) / 256, 256>>>(theta, lnC_r, lnC_i);   // 0
    k_xp<<<dim3(Tq / 32, Bq), 256>>>(x, R);                                    // 1
    k_states<<<Bq * Kq, 256>>>();                                              // 2
    k_gemm<<<dim3(ROWS / MT, 2), 128>>>(out);                                  // 3
    k_dterm<<<(Bq * Tq) / 8, 128>>>(Dmat, Dov, out);                           // 4
}